// round 10
// baseline (speedup 1.0000x reference)
#include <cuda_runtime.h>
#include <cuda_bf16.h>
#include <cstdint>
#include <cstddef>

#define BATCH 2
#define SEQ   2048
#define DIM   1024
#define NHEAD 16
#define HD    64
// SCALE * log2(e): logits kept in base-2 domain (folded into Q at QKV epilogue)
#define SC2   0.18033688011112042f

// ---------------------------------------------------------------------------
// Scratch (allocation-free rule: __device__ globals)
// ---------------------------------------------------------------------------
__device__ __nv_bfloat16 g_xhi[(size_t)BATCH * SEQ * DIM];
__device__ __nv_bfloat16 g_xlo[(size_t)BATCH * SEQ * DIM];
__device__ __nv_bfloat16 g_qh [(size_t)BATCH * SEQ * 3 * DIM];   // qkv hi
__device__ __nv_bfloat16 g_ql [(size_t)BATCH * SEQ * 3 * DIM];   // qkv lo
__device__ __nv_bfloat16 g_ahi[(size_t)BATCH * SEQ * DIM];       // attn hi
__device__ __nv_bfloat16 g_alo[(size_t)BATCH * SEQ * DIM];       // attn lo
__device__ __nv_bfloat16 g_wqhi[(size_t)3 * DIM * DIM];          // [3072,1024] K-major
__device__ __nv_bfloat16 g_wqlo[(size_t)3 * DIM * DIM];
__device__ __nv_bfloat16 g_wphi[(size_t)DIM * DIM];
__device__ __nv_bfloat16 g_wplo[(size_t)DIM * DIM];

// ---------------------------------------------------------------------------
// Portable PTX helpers
// ---------------------------------------------------------------------------
__device__ __forceinline__ uint32_t smem_u32(const void* p) {
    uint32_t a;
    asm("{ .reg .u64 t; cvta.to.shared.u64 t, %1; cvt.u32.u64 %0, t; }" : "=r"(a) : "l"(p));
    return a;
}
#define CPA16(dst, src) \
    asm volatile("cp.async.cg.shared.global [%0], [%1], 16;" :: "r"(dst), "l"(src) : "memory")
#define CP_COMMIT() asm volatile("cp.async.commit_group;" ::: "memory")
#define CP_WAIT0()  asm volatile("cp.async.wait_group 0;" ::: "memory")
#define CP_WAIT1()  asm volatile("cp.async.wait_group 1;" ::: "memory")

#define LDSM_X4(r, addr) \
    asm volatile("ldmatrix.sync.aligned.m8n8.x4.shared.b16 {%0,%1,%2,%3}, [%4];" \
        : "=r"((r)[0]), "=r"((r)[1]), "=r"((r)[2]), "=r"((r)[3]) : "r"(addr))
#define LDSM_X4T(r, addr) \
    asm volatile("ldmatrix.sync.aligned.m8n8.x4.trans.shared.b16 {%0,%1,%2,%3}, [%4];" \
        : "=r"((r)[0]), "=r"((r)[1]), "=r"((r)[2]), "=r"((r)[3]) : "r"(addr))

#define MMA16816(c, a, b) \
    asm volatile("mma.sync.aligned.m16n8k16.row.col.f32.bf16.bf16.f32 " \
        "{%0,%1,%2,%3}, {%4,%5,%6,%7}, {%8,%9}, {%0,%1,%2,%3};" \
        : "+f"((c)[0]), "+f"((c)[1]), "+f"((c)[2]), "+f"((c)[3]) \
        : "r"((a)[0]), "r"((a)[1]), "r"((a)[2]), "r"((a)[3]), "r"((b)[0]), "r"((b)[1]))

#define SWZ64(off)  ((off) ^ (((off) >> 3) & 0x30))
#define SWZ128(off) ((off) ^ (((off) >> 3) & 0x70))

__device__ __forceinline__ float ex2f(float x) {
    float y; asm("ex2.approx.ftz.f32 %0, %1;" : "=f"(y) : "f"(x)); return y;
}
__device__ __forceinline__ uint32_t pack_bf2(float lo, float hi) {
    __nv_bfloat162 h = __floats2bfloat162_rn(lo, hi);
    return *(uint32_t*)&h;
}

// ---------------------------------------------------------------------------
// Preprocessing
// ---------------------------------------------------------------------------
__global__ __launch_bounds__(256) void split_kernel(
    const float* __restrict__ X, __nv_bfloat16* __restrict__ hi,
    __nv_bfloat16* __restrict__ lo, int n4)
{
    int i = blockIdx.x * blockDim.x + threadIdx.x;
    if (i >= n4) return;
    float4 v = ((const float4*)X)[i];
    __nv_bfloat16 h[4], l[4];
    float f[4] = {v.x, v.y, v.z, v.w};
    #pragma unroll
    for (int j = 0; j < 4; j++) {
        h[j] = __float2bfloat16(f[j]);
        l[j] = __float2bfloat16(f[j] - __bfloat162float(h[j]));
    }
    ((uint2*)hi)[i] = *(uint2*)h;
    ((uint2*)lo)[i] = *(uint2*)l;
}

__global__ __launch_bounds__(256) void transpose_split(
    const float* __restrict__ W, __nv_bfloat16* __restrict__ Thi,
    __nv_bfloat16* __restrict__ Tlo, int K, int N)
{
    __shared__ float tile[32][33];
    int tx = threadIdx.x & 31, ty = threadIdx.x >> 5;
    int k0 = blockIdx.y * 32, n0 = blockIdx.x * 32;
    #pragma unroll
    for (int i = 0; i < 32; i += 8)
        tile[ty + i][tx] = W[(size_t)(k0 + ty + i) * N + n0 + tx];
    __syncthreads();
    #pragma unroll
    for (int i = 0; i < 32; i += 8) {
        float v = tile[tx][ty + i];
        __nv_bfloat16 h = __float2bfloat16(v);
        __nv_bfloat16 l = __float2bfloat16(v - __bfloat162float(h));
        size_t o = (size_t)(n0 + ty + i) * K + k0 + tx;
        Thi[o] = h; Tlo[o] = l;
    }
}

// ---------------------------------------------------------------------------
// HMMA bf16-split GEMM: C = A[M,K] @ T[N,K]^T, fp32 or bf16-hi/lo output
// CTA 128x128, BK=32, 3-stage cp.async, fragment-pipelined, 2 CTAs/SM.
// SPLIT epilogue scales by SC2 for the Q columns (colBase < DIM).
// ---------------------------------------------------------------------------
#define GST 32768
#define GSMEM_TOTAL (3 * GST)

#define LOAD_STAGE(sidx, kc) do {                                              \
    uint32_t sb = sbase + (uint32_t)(sidx) * GST;                              \
    _Pragma("unroll")                                                          \
    for (int t_ = 0; t_ < 2; ++t_) {                                           \
        int v_ = tid + t_ * 256;                                               \
        int row_ = v_ >> 2, cb_ = v_ & 3;                                      \
        uint32_t sw_ = SWZ64((uint32_t)(row_ * 64 + cb_ * 16));                \
        size_t gA_ = (size_t)(rowBase + row_) * K + (kc) + cb_ * 8;            \
        size_t gB_ = (size_t)(colBase + row_) * K + (kc) + cb_ * 8;            \
        CPA16(sb + sw_,         (const char*)(Ahi + gA_));                     \
        CPA16(sb + 8192  + sw_, (const char*)(Alo + gA_));                     \
        CPA16(sb + 16384 + sw_, (const char*)(Bhi + gB_));                     \
        CPA16(sb + 24576 + sw_, (const char*)(Blo + gB_));                     \
    }                                                                          \
} while (0)

template <bool SPLIT>
__global__ __launch_bounds__(256, 2) void gemm_mma(
    const __nv_bfloat16* __restrict__ Ahi, const __nv_bfloat16* __restrict__ Alo,
    const __nv_bfloat16* __restrict__ Bhi, const __nv_bfloat16* __restrict__ Blo,
    float* __restrict__ C, __nv_bfloat16* __restrict__ Chi,
    __nv_bfloat16* __restrict__ Clo, int M, int N, int K)
{
    extern __shared__ char smem[];
    const uint32_t sbase = smem_u32(smem);
    const int tid  = threadIdx.x;
    const int lane = tid & 31;
    const int wid  = tid >> 5;
    const int wm = (wid & 3) * 32;
    const int wn = (wid >> 2) * 64;
    const int rowBase = blockIdx.y * 128;
    const int colBase = blockIdx.x * 128;

    const int mi = lane >> 3;
    const uint32_t a_off = (uint32_t)((((mi & 1) * 8 + (lane & 7)) * 64) + (mi >> 1) * 16);
    const uint32_t b_off = (uint32_t)((((mi >> 1) * 8 + (lane & 7)) * 64) + (mi & 1) * 16);

    float acc[2][8][4];
    #pragma unroll
    for (int i = 0; i < 2; i++)
        #pragma unroll
        for (int j = 0; j < 8; j++)
            #pragma unroll
            for (int q = 0; q < 4; q++) acc[i][j][q] = 0.f;

    const int nk = K / 32;                 // 32
    LOAD_STAGE(0, 0);  CP_COMMIT();
    LOAD_STAGE(1, 32); CP_COMMIT();

    int sidx = 0;                          // stage of chunk c (mod 3)
    for (int c = 0; c < nk; ++c) {
        if (c + 1 < nk) { CP_WAIT1(); } else { CP_WAIT0(); }
        __syncthreads();                   // all warps done with compute(c-1)
        if (c + 2 < nk) {
            int ns = sidx + 2; if (ns >= 3) ns -= 3;
            LOAD_STAGE(ns, (c + 2) * 32);
            CP_COMMIT();
        }

        const uint32_t st = sbase + (uint32_t)sidx * GST;

        // hoist all A fragments for this chunk (both kb halves)
        uint32_t Ah[2][2][4], Al[2][2][4];
        #pragma unroll
        for (int kb2 = 0; kb2 < 2; kb2++)
            #pragma unroll
            for (int i = 0; i < 2; i++) {
                uint32_t off = (uint32_t)((wm + i * 16) * 64 + kb2 * 32) + a_off;
                LDSM_X4(Ah[kb2][i], st + SWZ64(off));
                LDSM_X4(Al[kb2][i], st + 8192 + SWZ64(off));
            }

        // B fragments double-buffered across the flattened (kb, jp) loop
        uint32_t Bh[2][4], Bl[2][4];
        {
            uint32_t off = (uint32_t)(wn * 64) + b_off;   // kb=0, jp=0
            LDSM_X4(Bh[0], st + 16384 + SWZ64(off));
            LDSM_X4(Bl[0], st + 24576 + SWZ64(off));
        }
        int bb = 0;
        #pragma unroll
        for (int it = 0; it < 8; it++) {            // it = kb*4 + jp
            const int kb = it >> 2, jp = it & 3;
            if (it + 1 < 8) {
                const int nkb = (it + 1) >> 2, njp = (it + 1) & 3;
                uint32_t off = (uint32_t)((wn + njp * 16) * 64 + nkb * 32) + b_off;
                LDSM_X4(Bh[bb ^ 1], st + 16384 + SWZ64(off));
                LDSM_X4(Bl[bb ^ 1], st + 24576 + SWZ64(off));
            }
            // product-major MMAs (12) using prefetched fragments
            #pragma unroll
            for (int i = 0; i < 2; i++)
                #pragma unroll
                for (int jj = 0; jj < 2; jj++)
                    MMA16816(acc[i][jp * 2 + jj], Ah[kb][i], (&Bh[bb][jj * 2]));
            #pragma unroll
            for (int i = 0; i < 2; i++)
                #pragma unroll
                for (int jj = 0; jj < 2; jj++)
                    MMA16816(acc[i][jp * 2 + jj], Ah[kb][i], (&Bl[bb][jj * 2]));
            #pragma unroll
            for (int i = 0; i < 2; i++)
                #pragma unroll
                for (int jj = 0; jj < 2; jj++)
                    MMA16816(acc[i][jp * 2 + jj], Al[kb][i], (&Bh[bb][jj * 2]));
            bb ^= 1;
        }
        ++sidx; if (sidx >= 3) sidx = 0;
    }

    // SC2 folded into Q columns (SPLIT path only; colBase uniform per CTA)
    const float oscale = (SPLIT && colBase < DIM) ? SC2 : 1.0f;

    #pragma unroll
    for (int i = 0; i < 2; i++) {
        #pragma unroll
        for (int j = 0; j < 8; j++) {
            int r0 = rowBase + wm + i * 16 + (lane >> 2);
            int c0 = colBase + wn + j * 8 + (lane & 3) * 2;
            if (SPLIT) {
                #pragma unroll
                for (int hh = 0; hh < 2; hh++) {
                    float v0 = acc[i][j][hh * 2] * oscale, v1 = acc[i][j][hh * 2 + 1] * oscale;
                    __nv_bfloat162 h2 = __floats2bfloat162_rn(v0, v1);
                    float l0 = v0 - __bfloat162float(h2.x);
                    float l1 = v1 - __bfloat162float(h2.y);
                    size_t idx = ((size_t)(r0 + hh * 8) * N + c0) >> 1;
                    ((uint32_t*)Chi)[idx] = *(uint32_t*)&h2;
                    ((uint32_t*)Clo)[idx] = pack_bf2(l0, l1);
                }
            } else {
                *(float2*)&C[(size_t)r0 * N + c0]       = make_float2(acc[i][j][0], acc[i][j][1]);
                *(float2*)&C[(size_t)(r0 + 8) * N + c0] = make_float2(acc[i][j][2], acc[i][j][3]);
            }
        }
    }
}

// ---------------------------------------------------------------------------
// Flash attention, HMMA. CTA = 128 q rows of one (b,h); 8 warps x 16 rows.
// Bc=64: stage 32KB, 2 stages + Q 32KB = 96KB; 2 CTAs/SM.
// Fragment-pipelined QK and PV loops; exp interleaved with PV.
// Q already scaled by SC2 at the QKV-GEMM epilogue.
// ---------------------------------------------------------------------------
#define FST     32768
#define F_KHI   0
#define F_KLO   8192
#define F_VHI   16384
#define F_VLO   24576
#define FQ_OFF  (2 * FST)
#define FSMEM_TOTAL (2 * FST + 32768)

#define FLOAD_KV(sidx, c0b) do {                                               \
    uint32_t sb = sbase + (uint32_t)(sidx) * FST;                              \
    _Pragma("unroll")                                                          \
    for (int t_ = 0; t_ < 2; ++t_) {                                           \
        int v_ = tid + t_ * 256;                                               \
        int row_ = v_ >> 3, ch_ = v_ & 7;                                      \
        uint32_t sw_ = SWZ128((uint32_t)(row_ * 128 + ch_ * 16));              \
        size_t base_ = ((size_t)(bS + (c0b) + row_) * 3) * DIM + hHD + ch_ * 8;\
        CPA16(sb + F_KHI + sw_, (const char*)(qh + base_ + DIM));              \
        CPA16(sb + F_KLO + sw_, (const char*)(ql + base_ + DIM));              \
        CPA16(sb + F_VHI + sw_, (const char*)(qh + base_ + 2 * DIM));          \
        CPA16(sb + F_VLO + sw_, (const char*)(ql + base_ + 2 * DIM));          \
    }                                                                          \
} while (0)

__global__ __launch_bounds__(256, 2) void flash_mma(
    const __nv_bfloat16* __restrict__ qh, const __nv_bfloat16* __restrict__ ql,
    __nv_bfloat16* __restrict__ Ahi, __nv_bfloat16* __restrict__ Alo)
{
    extern __shared__ char smem[];
    const uint32_t sbase = smem_u32(smem);
    const int tid  = threadIdx.x;
    const int lane = tid & 31;
    const int wid  = tid >> 5;
    const int wrow = wid * 16;
    const int h  = blockIdx.y;
    const int b  = blockIdx.z;
    const int q0 = blockIdx.x * 128;
    const int bS  = b * SEQ;
    const int hHD = h * HD;

    const int mi = lane >> 3;
    const uint32_t a_row = (mi & 1) * 8 + (lane & 7);
    const uint32_t a_ch  = (mi >> 1) * 16;
    const uint32_t b_row = (mi >> 1) * 8 + (lane & 7);
    const uint32_t b_ch  = (mi & 1) * 16;

    // Q tile (once) + first KV stage
    {
        #pragma unroll
        for (int t_ = 0; t_ < 4; ++t_) {
            int v_ = tid + t_ * 256;
            int row_ = v_ >> 3, ch_ = v_ & 7;
            uint32_t sw_ = SWZ128((uint32_t)(row_ * 128 + ch_ * 16));
            size_t base_ = ((size_t)(bS + q0 + row_) * 3) * DIM + hHD + ch_ * 8;
            CPA16(sbase + FQ_OFF + sw_,         (const char*)(qh + base_));
            CPA16(sbase + FQ_OFF + 16384 + sw_, (const char*)(ql + base_));
        }
        FLOAD_KV(0, 0);
        CP_COMMIT();
    }

    float S[8][4];
    float O[8][4];
    #pragma unroll
    for (int j = 0; j < 8; j++)
        #pragma unroll
        for (int q = 0; q < 4; q++) O[j][q] = 0.f;
    float mA = -1e30f, mB = -1e30f, lA = 0.f, lB = 0.f;

    const int ntiles = SEQ / 64;   // 32

    for (int tI = 0; tI < ntiles; ++tI) {
        const int s = tI & 1;
        CP_WAIT0();
        __syncthreads();               // all warps done with compute(tI-1)
        if (tI + 1 < ntiles) { FLOAD_KV((tI + 1) & 1, (tI + 1) * 64); CP_COMMIT(); }

        const uint32_t st = sbase + (uint32_t)s * FST;

        // ---- S = Q K^T (pipelined: K fragments double-buffered) ----
        #pragma unroll
        for (int nb = 0; nb < 8; nb++)
            #pragma unroll
            for (int q = 0; q < 4; q++) S[nb][q] = 0.f;

        uint32_t Kh[2][4], Kl[2][4];
        {
            uint32_t koff = SWZ128((uint32_t)(b_row * 128) + b_ch);   // dks=0, nbp=0
            LDSM_X4(Kh[0], st + F_KHI + koff);
            LDSM_X4(Kl[0], st + F_KLO + koff);
        }
        uint32_t qhi[4], qlo[4];
        int kb = 0;
        #pragma unroll
        for (int it = 0; it < 16; it++) {           // it = dks*4 + nbp
            const int dks = it >> 2, nbp = it & 3;
            if (nbp == 0) {
                uint32_t qoff = SWZ128((uint32_t)((wrow + a_row) * 128 + dks * 32) + a_ch);
                LDSM_X4(qhi, sbase + FQ_OFF + qoff);
                LDSM_X4(qlo, sbase + FQ_OFF + 16384 + qoff);
            }
            if (it + 1 < 16) {
                const int nd = (it + 1) >> 2, nn = (it + 1) & 3;
                uint32_t koff = SWZ128((uint32_t)((nn * 16 + b_row) * 128 + nd * 32) + b_ch);
                LDSM_X4(Kh[kb ^ 1], st + F_KHI + koff);
                LDSM_X4(Kl[kb ^ 1], st + F_KLO + koff);
            }
            float* s0 = S[nbp * 2 + 0];
            float* s1 = S[nbp * 2 + 1];
            MMA16816(s0, qhi, (&Kh[kb][0]));
            MMA16816(s1, qhi, (&Kh[kb][2]));
            MMA16816(s0, qhi, (&Kl[kb][0]));
            MMA16816(s1, qhi, (&Kl[kb][2]));
            MMA16816(s0, qlo, (&Kh[kb][0]));
            MMA16816(s1, qlo, (&Kh[kb][2]));
            kb ^= 1;
        }

        // ---- row max + O rescale ----
        float mxA = -1e30f, mxB = -1e30f;
        #pragma unroll
        for (int nb = 0; nb < 8; nb++) {
            mxA = fmaxf(mxA, fmaxf(S[nb][0], S[nb][1]));
            mxB = fmaxf(mxB, fmaxf(S[nb][2], S[nb][3]));
        }
        #pragma unroll
        for (int d = 1; d <= 2; d <<= 1) {
            mxA = fmaxf(mxA, __shfl_xor_sync(0xffffffffu, mxA, d));
            mxB = fmaxf(mxB, __shfl_xor_sync(0xffffffffu, mxB, d));
        }
        float mAn = fmaxf(mA, mxA), mBn = fmaxf(mB, mxB);
        float fA = ex2f(mA - mAn),  fB = ex2f(mB - mBn);
        #pragma unroll
        for (int j = 0; j < 8; j++) {
            O[j][0] *= fA; O[j][1] *= fA; O[j][2] *= fB; O[j][3] *= fB;
        }

        // ---- PV (pipelined: V fragments double-buffered; exp interleaved) ----
        float sA = 0.f, sB = 0.f;
        uint32_t Vh[2][4], Vl[2][4];
        {
            uint32_t voff = SWZ128((uint32_t)(a_row * 128) + a_ch);   // ks=0, dg=0
            LDSM_X4T(Vh[0], st + F_VHI + voff);
            LDSM_X4T(Vl[0], st + F_VLO + voff);
        }
        uint32_t ph[4], pl[4];
        int vb = 0;
        #pragma unroll
        for (int it = 0; it < 16; it++) {           // it = ks*4 + dg
            const int ks = it >> 2, dg = it & 3;
            if (dg == 0) {
                float pv[2][4];
                #pragma unroll
                for (int jj = 0; jj < 2; jj++) {
                    const float* sv = S[ks * 2 + jj];
                    pv[jj][0] = ex2f(sv[0] - mAn);
                    pv[jj][1] = ex2f(sv[1] - mAn);
                    pv[jj][2] = ex2f(sv[2] - mBn);
                    pv[jj][3] = ex2f(sv[3] - mBn);
                    sA += pv[jj][0] + pv[jj][1];
                    sB += pv[jj][2] + pv[jj][3];
                }
                #pragma unroll
                for (int u = 0; u < 4; u++) {
                    const float* sv = pv[u >> 1];
                    float x0 = sv[(u & 1) * 2], x1 = sv[(u & 1) * 2 + 1];
                    __nv_bfloat162 h2 = __floats2bfloat162_rn(x0, x1);
                    ph[u] = *(uint32_t*)&h2;
                    pl[u] = pack_bf2(x0 - __bfloat162float(h2.x), x1 - __bfloat162float(h2.y));
                }
            }
            if (it + 1 < 16) {
                const int nks = (it + 1) >> 2, ndg = (it + 1) & 3;
                uint32_t voff = SWZ128((uint32_t)((nks * 16 + a_row) * 128 + ndg * 32) + a_ch);
                LDSM_X4T(Vh[vb ^ 1], st + F_VHI + voff);
                LDSM_X4T(Vl[vb ^ 1], st + F_VLO + voff);
            }
            float* o0 = O[dg * 2 + 0];
            float* o1 = O[dg * 2 + 1];
            MMA16816(o0, ph, (&Vh[vb][0]));
            MMA16816(o1, ph, (&Vh[vb][2]));
            MMA16816(o0, ph, (&Vl[vb][0]));
            MMA16816(o1, ph, (&Vl[vb][2]));
            MMA16816(o0, pl, (&Vh[vb][0]));
            MMA16816(o1, pl, (&Vh[vb][2]));
            vb ^= 1;
        }
        #pragma unroll
        for (int d = 1; d <= 2; d <<= 1) {
            sA += __shfl_xor_sync(0xffffffffu, sA, d);
            sB += __shfl_xor_sync(0xffffffffu, sB, d);
        }
        lA = lA * fA + sA;  lB = lB * fB + sB;
        mA = mAn;           mB = mBn;
    }

    // ---- epilogue: normalize, split to bf16 hi/lo, store ----
    float invA = 1.f / lA, invB = 1.f / lB;
    int rA = bS + q0 + wrow + (lane >> 2);
    int rB = rA + 8;
    #pragma unroll
    for (int j = 0; j < 8; j++) {
        int d0 = j * 8 + (lane & 3) * 2;
        float a0 = O[j][0] * invA, a1 = O[j][1] * invA;
        float b0 = O[j][2] * invB, b1 = O[j][3] * invB;
        __nv_bfloat162 hA = __floats2bfloat162_rn(a0, a1);
        __nv_bfloat162 hB = __floats2bfloat162_rn(b0, b1);
        size_t iA = ((size_t)rA * DIM + hHD + d0) >> 1;
        size_t iB = ((size_t)rB * DIM + hHD + d0) >> 1;
        ((uint32_t*)Ahi)[iA] = *(uint32_t*)&hA;
        ((uint32_t*)Ahi)[iB] = *(uint32_t*)&hB;
        ((uint32_t*)Alo)[iA] = pack_bf2(a0 - __bfloat162float(hA.x), a1 - __bfloat162float(hA.y));
        ((uint32_t*)Alo)[iB] = pack_bf2(b0 - __bfloat162float(hB.x), b1 - __bfloat162float(hB.y));
    }
}

// ---------------------------------------------------------------------------
extern "C" void kernel_launch(void* const* d_in, const int* in_sizes, int n_in,
                              void* d_out, int out_size)
{
    const float* x     = (const float*)d_in[0];
    const float* Wqkv  = (const float*)d_in[1];
    const float* Wproj = (const float*)d_in[2];
    float* out = (float*)d_out;

    __nv_bfloat16 *xhi, *xlo, *qh, *ql, *ahi, *alo, *wqhi, *wqlo, *wphi, *wplo;
    cudaGetSymbolAddress((void**)&xhi,  g_xhi);
    cudaGetSymbolAddress((void**)&xlo,  g_xlo);
    cudaGetSymbolAddress((void**)&qh,   g_qh);
    cudaGetSymbolAddress((void**)&ql,   g_ql);
    cudaGetSymbolAddress((void**)&ahi,  g_ahi);
    cudaGetSymbolAddress((void**)&alo,  g_alo);
    cudaGetSymbolAddress((void**)&wqhi, g_wqhi);
    cudaGetSymbolAddress((void**)&wqlo, g_wqlo);
    cudaGetSymbolAddress((void**)&wphi, g_wphi);
    cudaGetSymbolAddress((void**)&wplo, g_wplo);

    const int M = BATCH * SEQ;          // 4096

    cudaFuncSetAttribute(gemm_mma<true>,  cudaFuncAttributeMaxDynamicSharedMemorySize, GSMEM_TOTAL);
    cudaFuncSetAttribute(gemm_mma<false>, cudaFuncAttributeMaxDynamicSharedMemorySize, GSMEM_TOTAL);
    cudaFuncSetAttribute(flash_mma,       cudaFuncAttributeMaxDynamicSharedMemorySize, FSMEM_TOTAL);

    // 0) splits
    split_kernel<<<(M * DIM / 4 + 255) / 256, 256>>>(x, xhi, xlo, M * DIM / 4);
    {
        dim3 g1(3 * DIM / 32, DIM / 32);
        transpose_split<<<g1, 256>>>(Wqkv, wqhi, wqlo, DIM, 3 * DIM);
        dim3 g2(DIM / 32, DIM / 32);
        transpose_split<<<g2, 256>>>(Wproj, wphi, wplo, DIM, DIM);
    }

    // 1) qkv = x @ Wqkv -> bf16 hi/lo directly (Q columns pre-scaled by SC2)
    {
        dim3 grid(3 * DIM / 128, M / 128);
        gemm_mma<true><<<grid, 256, GSMEM_TOTAL>>>(xhi, xlo, wqhi, wqlo,
                                                   nullptr, qh, ql, M, 3 * DIM, DIM);
    }

    // 2) flash attention (HMMA) -> bf16 hi/lo directly
    {
        dim3 grid(SEQ / 128, NHEAD, BATCH);
        flash_mma<<<grid, 256, FSMEM_TOTAL>>>(qh, ql, ahi, alo);
    }

    // 3) out = attn @ Wproj (fp32 out)
    {
        dim3 grid(DIM / 128, M / 128);
        gemm_mma<false><<<grid, 256, GSMEM_TOTAL>>>(ahi, alo, wphi, wplo,
                                                    out, nullptr, nullptr, M, DIM, DIM);
    }
}

// round 11
// speedup vs baseline: 1.4366x; 1.4366x over previous
#include <cuda_runtime.h>
#include <cuda_fp16.h>
#include <cstdint>
#include <cstddef>

#define BATCH 2
#define SEQ   2048
#define DIM   1024
#define NHEAD 16
#define HD    64
// SCALE * log2(e): logits kept in base-2 domain (folded into Q at QKV epilogue)
#define SC2   0.18033688011112042f

// ---------------------------------------------------------------------------
// Scratch (allocation-free rule: __device__ globals) — fp16 scheme
// ---------------------------------------------------------------------------
__device__ __half g_xhi[(size_t)BATCH * SEQ * DIM];
__device__ __half g_xlo[(size_t)BATCH * SEQ * DIM];
__device__ __half g_qh [(size_t)BATCH * SEQ * 3 * DIM];   // qkv hi
__device__ __half g_ql [(size_t)BATCH * SEQ * 3 * DIM];   // qkv lo (only Q read)
__device__ __half g_ahi[(size_t)BATCH * SEQ * DIM];       // attn hi
__device__ __half g_alo[(size_t)BATCH * SEQ * DIM];       // attn lo
__device__ __half g_wqh[(size_t)3 * DIM * DIM];           // [3072,1024] K-major, hi only
__device__ __half g_wph[(size_t)DIM * DIM];               // [1024,1024] K-major, hi only

// ---------------------------------------------------------------------------
// Portable PTX helpers
// ---------------------------------------------------------------------------
__device__ __forceinline__ uint32_t smem_u32(const void* p) {
    uint32_t a;
    asm("{ .reg .u64 t; cvta.to.shared.u64 t, %1; cvt.u32.u64 %0, t; }" : "=r"(a) : "l"(p));
    return a;
}
#define CPA16(dst, src) \
    asm volatile("cp.async.cg.shared.global [%0], [%1], 16;" :: "r"(dst), "l"(src) : "memory")
#define CP_COMMIT() asm volatile("cp.async.commit_group;" ::: "memory")
#define CP_WAIT0()  asm volatile("cp.async.wait_group 0;" ::: "memory")
#define CP_WAIT1()  asm volatile("cp.async.wait_group 1;" ::: "memory")

#define LDSM_X4(r, addr) \
    asm volatile("ldmatrix.sync.aligned.m8n8.x4.shared.b16 {%0,%1,%2,%3}, [%4];" \
        : "=r"((r)[0]), "=r"((r)[1]), "=r"((r)[2]), "=r"((r)[3]) : "r"(addr))
#define LDSM_X4T(r, addr) \
    asm volatile("ldmatrix.sync.aligned.m8n8.x4.trans.shared.b16 {%0,%1,%2,%3}, [%4];" \
        : "=r"((r)[0]), "=r"((r)[1]), "=r"((r)[2]), "=r"((r)[3]) : "r"(addr))

// fp16 HMMA, fp32 accumulate
#define MMA16816(c, a, b) \
    asm volatile("mma.sync.aligned.m16n8k16.row.col.f32.f16.f16.f32 " \
        "{%0,%1,%2,%3}, {%4,%5,%6,%7}, {%8,%9}, {%0,%1,%2,%3};" \
        : "+f"((c)[0]), "+f"((c)[1]), "+f"((c)[2]), "+f"((c)[3]) \
        : "r"((a)[0]), "r"((a)[1]), "r"((a)[2]), "r"((a)[3]), "r"((b)[0]), "r"((b)[1]))

#define SWZ64(off)  ((off) ^ (((off) >> 3) & 0x30))
#define SWZ128(off) ((off) ^ (((off) >> 3) & 0x70))

__device__ __forceinline__ float ex2f(float x) {
    float y; asm("ex2.approx.ftz.f32 %0, %1;" : "=f"(y) : "f"(x)); return y;
}
__device__ __forceinline__ uint32_t pack_hf2(float a, float b) {
    __half2 h = __floats2half2_rn(a, b);
    return *(uint32_t*)&h;
}

// ---------------------------------------------------------------------------
// Preprocessing
// ---------------------------------------------------------------------------
__global__ __launch_bounds__(256) void split_kernel(
    const float* __restrict__ X, __half* __restrict__ hi,
    __half* __restrict__ lo, int n4)
{
    int i = blockIdx.x * blockDim.x + threadIdx.x;
    if (i >= n4) return;
    float4 v = ((const float4*)X)[i];
    __half h[4], l[4];
    float f[4] = {v.x, v.y, v.z, v.w};
    #pragma unroll
    for (int j = 0; j < 4; j++) {
        h[j] = __float2half_rn(f[j]);
        l[j] = __float2half_rn(f[j] - __half2float(h[j]));
    }
    ((uint2*)hi)[i] = *(uint2*)h;
    ((uint2*)lo)[i] = *(uint2*)l;
}

// W [K, N] fp32 -> T [N, K] fp16 hi only (transpose + quantize)
__global__ __launch_bounds__(256) void transpose_h(
    const float* __restrict__ W, __half* __restrict__ Th, int K, int N)
{
    __shared__ float tile[32][33];
    int tx = threadIdx.x & 31, ty = threadIdx.x >> 5;
    int k0 = blockIdx.y * 32, n0 = blockIdx.x * 32;
    #pragma unroll
    for (int i = 0; i < 32; i += 8)
        tile[ty + i][tx] = W[(size_t)(k0 + ty + i) * N + n0 + tx];
    __syncthreads();
    #pragma unroll
    for (int i = 0; i < 32; i += 8) {
        float v = tile[tx][ty + i];
        Th[(size_t)(n0 + ty + i) * K + k0 + tx] = __float2half_rn(v);
    }
}

// ---------------------------------------------------------------------------
// HMMA fp16 2-product GEMM: C = (Ahi+Alo)[M,K] @ Bh[N,K]^T
// CTA 128x128, BK=32, 3-stage cp.async, 2 CTAs/SM.
// Stage (24KB): Ahi[0,8K) Alo[8K,16K) Bh[16K,24K)
// ---------------------------------------------------------------------------
#define GST 24576
#define GSMEM_TOTAL (3 * GST)

#define LOAD_STAGE(sidx, kc) do {                                              \
    uint32_t sb = sbase + (uint32_t)(sidx) * GST;                              \
    _Pragma("unroll")                                                          \
    for (int t_ = 0; t_ < 2; ++t_) {                                           \
        int v_ = tid + t_ * 256;                                               \
        int row_ = v_ >> 2, cb_ = v_ & 3;                                      \
        uint32_t sw_ = SWZ64((uint32_t)(row_ * 64 + cb_ * 16));                \
        size_t gA_ = (size_t)(rowBase + row_) * K + (kc) + cb_ * 8;            \
        size_t gB_ = (size_t)(colBase + row_) * K + (kc) + cb_ * 8;            \
        CPA16(sb + sw_,         (const char*)(Ahi + gA_));                     \
        CPA16(sb + 8192  + sw_, (const char*)(Alo + gA_));                     \
        CPA16(sb + 16384 + sw_, (const char*)(Bh + gB_));                      \
    }                                                                          \
} while (0)

template <bool SPLIT>
__global__ __launch_bounds__(256, 2) void gemm_mma(
    const __half* __restrict__ Ahi, const __half* __restrict__ Alo,
    const __half* __restrict__ Bh,
    float* __restrict__ C, __half* __restrict__ Chi,
    __half* __restrict__ Clo, int M, int N, int K)
{
    extern __shared__ char smem[];
    const uint32_t sbase = smem_u32(smem);
    const int tid  = threadIdx.x;
    const int lane = tid & 31;
    const int wid  = tid >> 5;
    const int wm = (wid & 3) * 32;
    const int wn = (wid >> 2) * 64;
    const int rowBase = blockIdx.y * 128;
    const int colBase = blockIdx.x * 128;

    const int mi = lane >> 3;
    const uint32_t a_off = (uint32_t)((((mi & 1) * 8 + (lane & 7)) * 64) + (mi >> 1) * 16);
    const uint32_t b_off = (uint32_t)((((mi >> 1) * 8 + (lane & 7)) * 64) + (mi & 1) * 16);

    float acc[2][8][4];
    #pragma unroll
    for (int i = 0; i < 2; i++)
        #pragma unroll
        for (int j = 0; j < 8; j++)
            #pragma unroll
            for (int q = 0; q < 4; q++) acc[i][j][q] = 0.f;

    const int nk = K / 32;                 // 32
    LOAD_STAGE(0, 0);  CP_COMMIT();
    LOAD_STAGE(1, 32); CP_COMMIT();

    int sidx = 0;
    for (int c = 0; c < nk; ++c) {
        if (c + 1 < nk) { CP_WAIT1(); } else { CP_WAIT0(); }
        __syncthreads();
        if (c + 2 < nk) {
            int ns = sidx + 2; if (ns >= 3) ns -= 3;
            LOAD_STAGE(ns, (c + 2) * 32);
            CP_COMMIT();
        }

        const uint32_t st = sbase + (uint32_t)sidx * GST;

        // hoist all A fragments for this chunk (both kb halves)
        uint32_t Ah[2][2][4], Al[2][2][4];
        #pragma unroll
        for (int kb2 = 0; kb2 < 2; kb2++)
            #pragma unroll
            for (int i = 0; i < 2; i++) {
                uint32_t off = (uint32_t)((wm + i * 16) * 64 + kb2 * 32) + a_off;
                LDSM_X4(Ah[kb2][i], st + SWZ64(off));
                LDSM_X4(Al[kb2][i], st + 8192 + SWZ64(off));
            }

        // B fragments double-buffered across the flattened (kb, jp) loop
        uint32_t Bf[2][4];
        {
            uint32_t off = (uint32_t)(wn * 64) + b_off;   // kb=0, jp=0
            LDSM_X4(Bf[0], st + 16384 + SWZ64(off));
        }
        int bb = 0;
        #pragma unroll
        for (int it = 0; it < 8; it++) {            // it = kb*4 + jp
            const int kb = it >> 2, jp = it & 3;
            if (it + 1 < 8) {
                const int nkb = (it + 1) >> 2, njp = (it + 1) & 3;
                uint32_t off = (uint32_t)((wn + njp * 16) * 64 + nkb * 32) + b_off;
                LDSM_X4(Bf[bb ^ 1], st + 16384 + SWZ64(off));
            }
            // 2-product: A-side exact, B-side fp16
            #pragma unroll
            for (int i = 0; i < 2; i++)
                #pragma unroll
                for (int jj = 0; jj < 2; jj++)
                    MMA16816(acc[i][jp * 2 + jj], Ah[kb][i], (&Bf[bb][jj * 2]));
            #pragma unroll
            for (int i = 0; i < 2; i++)
                #pragma unroll
                for (int jj = 0; jj < 2; jj++)
                    MMA16816(acc[i][jp * 2 + jj], Al[kb][i], (&Bf[bb][jj * 2]));
            bb ^= 1;
        }
        ++sidx; if (sidx >= 3) sidx = 0;
    }

    // SC2 folded into Q columns (SPLIT path only; colBase uniform per CTA)
    const float oscale = (SPLIT && colBase < DIM) ? SC2 : 1.0f;

    #pragma unroll
    for (int i = 0; i < 2; i++) {
        #pragma unroll
        for (int j = 0; j < 8; j++) {
            int r0 = rowBase + wm + i * 16 + (lane >> 2);
            int c0 = colBase + wn + j * 8 + (lane & 3) * 2;
            if (SPLIT) {
                #pragma unroll
                for (int hh = 0; hh < 2; hh++) {
                    float v0 = acc[i][j][hh * 2] * oscale, v1 = acc[i][j][hh * 2 + 1] * oscale;
                    __half2 h2 = __floats2half2_rn(v0, v1);
                    float l0 = v0 - __half2float(h2.x);
                    float l1 = v1 - __half2float(h2.y);
                    size_t idx = ((size_t)(r0 + hh * 8) * N + c0) >> 1;
                    ((uint32_t*)Chi)[idx] = *(uint32_t*)&h2;
                    ((uint32_t*)Clo)[idx] = pack_hf2(l0, l1);
                }
            } else {
                *(float2*)&C[(size_t)r0 * N + c0]       = make_float2(acc[i][j][0], acc[i][j][1]);
                *(float2*)&C[(size_t)(r0 + 8) * N + c0] = make_float2(acc[i][j][2], acc[i][j][3]);
            }
        }
    }
}

// ---------------------------------------------------------------------------
// Flash attention, fp16 2-product. CTA = 128 q rows of one (b,h); 8 warps.
// Stage (16KB): Khi[0,8K) Vhi[8K,16K); 2 stages + Qhi/Qlo 32KB = 64KB.
// Q exact (hi+lo), K and V hi-only.
// ---------------------------------------------------------------------------
#define FST     16384
#define F_KHI   0
#define F_VHI   8192
#define FQ_OFF  (2 * FST)
#define FSMEM_TOTAL (2 * FST + 32768)

#define FLOAD_KV(sidx, c0b) do {                                               \
    uint32_t sb = sbase + (uint32_t)(sidx) * FST;                              \
    _Pragma("unroll")                                                          \
    for (int t_ = 0; t_ < 2; ++t_) {                                           \
        int v_ = tid + t_ * 256;                                               \
        int row_ = v_ >> 3, ch_ = v_ & 7;                                      \
        uint32_t sw_ = SWZ128((uint32_t)(row_ * 128 + ch_ * 16));              \
        size_t base_ = ((size_t)(bS + (c0b) + row_) * 3) * DIM + hHD + ch_ * 8;\
        CPA16(sb + F_KHI + sw_, (const char*)(qh + base_ + DIM));              \
        CPA16(sb + F_VHI + sw_, (const char*)(qh + base_ + 2 * DIM));          \
    }                                                                          \
} while (0)

__global__ __launch_bounds__(256, 2) void flash_mma(
    const __half* __restrict__ qh, const __half* __restrict__ ql,
    __half* __restrict__ Ahi, __half* __restrict__ Alo)
{
    extern __shared__ char smem[];
    const uint32_t sbase = smem_u32(smem);
    const int tid  = threadIdx.x;
    const int lane = tid & 31;
    const int wid  = tid >> 5;
    const int wrow = wid * 16;
    const int h  = blockIdx.y;
    const int b  = blockIdx.z;
    const int q0 = blockIdx.x * 128;
    const int bS  = b * SEQ;
    const int hHD = h * HD;

    const int mi = lane >> 3;
    const uint32_t a_row = (mi & 1) * 8 + (lane & 7);
    const uint32_t a_ch  = (mi >> 1) * 16;
    const uint32_t b_row = (mi >> 1) * 8 + (lane & 7);
    const uint32_t b_ch  = (mi & 1) * 16;

    // Q tile (hi+lo, once) + first KV stage
    {
        #pragma unroll
        for (int t_ = 0; t_ < 4; ++t_) {
            int v_ = tid + t_ * 256;
            int row_ = v_ >> 3, ch_ = v_ & 7;
            uint32_t sw_ = SWZ128((uint32_t)(row_ * 128 + ch_ * 16));
            size_t base_ = ((size_t)(bS + q0 + row_) * 3) * DIM + hHD + ch_ * 8;
            CPA16(sbase + FQ_OFF + sw_,         (const char*)(qh + base_));
            CPA16(sbase + FQ_OFF + 16384 + sw_, (const char*)(ql + base_));
        }
        FLOAD_KV(0, 0);
        CP_COMMIT();
    }

    float S[8][4];
    float O[8][4];
    #pragma unroll
    for (int j = 0; j < 8; j++)
        #pragma unroll
        for (int q = 0; q < 4; q++) O[j][q] = 0.f;
    float mA = -1e30f, mB = -1e30f, lA = 0.f, lB = 0.f;

    const int ntiles = SEQ / 64;   // 32

    for (int tI = 0; tI < ntiles; ++tI) {
        const int s = tI & 1;
        CP_WAIT0();
        __syncthreads();
        if (tI + 1 < ntiles) { FLOAD_KV((tI + 1) & 1, (tI + 1) * 64); CP_COMMIT(); }

        const uint32_t st = sbase + (uint32_t)s * FST;

        // ---- S = Q K^T (2-product: Q exact, K hi-only) ----
        #pragma unroll
        for (int nb = 0; nb < 8; nb++)
            #pragma unroll
            for (int q = 0; q < 4; q++) S[nb][q] = 0.f;

        uint32_t Kh[2][4];
        {
            uint32_t koff = SWZ128((uint32_t)(b_row * 128) + b_ch);   // dks=0, nbp=0
            LDSM_X4(Kh[0], st + F_KHI + koff);
        }
        uint32_t qhi[4], qlo[4];
        int kb = 0;
        #pragma unroll
        for (int it = 0; it < 16; it++) {           // it = dks*4 + nbp
            const int dks = it >> 2, nbp = it & 3;
            if (nbp == 0) {
                uint32_t qoff = SWZ128((uint32_t)((wrow + a_row) * 128 + dks * 32) + a_ch);
                LDSM_X4(qhi, sbase + FQ_OFF + qoff);
                LDSM_X4(qlo, sbase + FQ_OFF + 16384 + qoff);
            }
            if (it + 1 < 16) {
                const int nd = (it + 1) >> 2, nn = (it + 1) & 3;
                uint32_t koff = SWZ128((uint32_t)((nn * 16 + b_row) * 128 + nd * 32) + b_ch);
                LDSM_X4(Kh[kb ^ 1], st + F_KHI + koff);
            }
            float* s0 = S[nbp * 2 + 0];
            float* s1 = S[nbp * 2 + 1];
            MMA16816(s0, qhi, (&Kh[kb][0]));
            MMA16816(s1, qhi, (&Kh[kb][2]));
            MMA16816(s0, qlo, (&Kh[kb][0]));
            MMA16816(s1, qlo, (&Kh[kb][2]));
            kb ^= 1;
        }

        // ---- row max + O rescale ----
        float mxA = -1e30f, mxB = -1e30f;
        #pragma unroll
        for (int nb = 0; nb < 8; nb++) {
            mxA = fmaxf(mxA, fmaxf(S[nb][0], S[nb][1]));
            mxB = fmaxf(mxB, fmaxf(S[nb][2], S[nb][3]));
        }
        #pragma unroll
        for (int d = 1; d <= 2; d <<= 1) {
            mxA = fmaxf(mxA, __shfl_xor_sync(0xffffffffu, mxA, d));
            mxB = fmaxf(mxB, __shfl_xor_sync(0xffffffffu, mxB, d));
        }
        float mAn = fmaxf(mA, mxA), mBn = fmaxf(mB, mxB);
        float fA = ex2f(mA - mAn),  fB = ex2f(mB - mBn);
        #pragma unroll
        for (int j = 0; j < 8; j++) {
            O[j][0] *= fA; O[j][1] *= fA; O[j][2] *= fB; O[j][3] *= fB;
        }

        // ---- PV (2-product: P exact, V hi-only; exp interleaved) ----
        float sA = 0.f, sB = 0.f;
        uint32_t Vh[2][4];
        {
            uint32_t voff = SWZ128((uint32_t)(a_row * 128) + a_ch);   // ks=0, dg=0
            LDSM_X4T(Vh[0], st + F_VHI + voff);
        }
        uint32_t ph[4], pl[4];
        int vb = 0;
        #pragma unroll
        for (int it = 0; it < 16; it++) {           // it = ks*4 + dg
            const int ks = it >> 2, dg = it & 3;
            if (dg == 0) {
                float pv[2][4];
                #pragma unroll
                for (int jj = 0; jj < 2; jj++) {
                    const float* sv = S[ks * 2 + jj];
                    pv[jj][0] = ex2f(sv[0] - mAn);
                    pv[jj][1] = ex2f(sv[1] - mAn);
                    pv[jj][2] = ex2f(sv[2] - mBn);
                    pv[jj][3] = ex2f(sv[3] - mBn);
                    sA += pv[jj][0] + pv[jj][1];
                    sB += pv[jj][2] + pv[jj][3];
                }
                #pragma unroll
                for (int u = 0; u < 4; u++) {
                    const float* sv = pv[u >> 1];
                    float x0 = sv[(u & 1) * 2], x1 = sv[(u & 1) * 2 + 1];
                    __half2 h2 = __floats2half2_rn(x0, x1);
                    ph[u] = *(uint32_t*)&h2;
                    pl[u] = pack_hf2(x0 - __half2float(h2.x), x1 - __half2float(h2.y));
                }
            }
            if (it + 1 < 16) {
                const int nks = (it + 1) >> 2, ndg = (it + 1) & 3;
                uint32_t voff = SWZ128((uint32_t)((nks * 16 + a_row) * 128 + ndg * 32) + a_ch);
                LDSM_X4T(Vh[vb ^ 1], st + F_VHI + voff);
            }
            float* o0 = O[dg * 2 + 0];
            float* o1 = O[dg * 2 + 1];
            MMA16816(o0, ph, (&Vh[vb][0]));
            MMA16816(o1, ph, (&Vh[vb][2]));
            MMA16816(o0, pl, (&Vh[vb][0]));
            MMA16816(o1, pl, (&Vh[vb][2]));
            vb ^= 1;
        }
        #pragma unroll
        for (int d = 1; d <= 2; d <<= 1) {
            sA += __shfl_xor_sync(0xffffffffu, sA, d);
            sB += __shfl_xor_sync(0xffffffffu, sB, d);
        }
        lA = lA * fA + sA;  lB = lB * fB + sB;
        mA = mAn;           mB = mBn;
    }

    // ---- epilogue: normalize, split to fp16 hi/lo, store ----
    float invA = 1.f / lA, invB = 1.f / lB;
    int rA = bS + q0 + wrow + (lane >> 2);
    int rB = rA + 8;
    #pragma unroll
    for (int j = 0; j < 8; j++) {
        int d0 = j * 8 + (lane & 3) * 2;
        float a0 = O[j][0] * invA, a1 = O[j][1] * invA;
        float b0 = O[j][2] * invB, b1 = O[j][3] * invB;
        __half2 hA = __floats2half2_rn(a0, a1);
        __half2 hB = __floats2half2_rn(b0, b1);
        size_t iA = ((size_t)rA * DIM + hHD + d0) >> 1;
        size_t iB = ((size_t)rB * DIM + hHD + d0) >> 1;
        ((uint32_t*)Ahi)[iA] = *(uint32_t*)&hA;
        ((uint32_t*)Ahi)[iB] = *(uint32_t*)&hB;
        ((uint32_t*)Alo)[iA] = pack_hf2(a0 - __half2float(hA.x), a1 - __half2float(hA.y));
        ((uint32_t*)Alo)[iB] = pack_hf2(b0 - __half2float(hB.x), b1 - __half2float(hB.y));
    }
}

// ---------------------------------------------------------------------------
extern "C" void kernel_launch(void* const* d_in, const int* in_sizes, int n_in,
                              void* d_out, int out_size)
{
    const float* x     = (const float*)d_in[0];
    const float* Wqkv  = (const float*)d_in[1];
    const float* Wproj = (const float*)d_in[2];
    float* out = (float*)d_out;

    __half *xhi, *xlo, *qh, *ql, *ahi, *alo, *wqh, *wph;
    cudaGetSymbolAddress((void**)&xhi, g_xhi);
    cudaGetSymbolAddress((void**)&xlo, g_xlo);
    cudaGetSymbolAddress((void**)&qh,  g_qh);
    cudaGetSymbolAddress((void**)&ql,  g_ql);
    cudaGetSymbolAddress((void**)&ahi, g_ahi);
    cudaGetSymbolAddress((void**)&alo, g_alo);
    cudaGetSymbolAddress((void**)&wqh, g_wqh);
    cudaGetSymbolAddress((void**)&wph, g_wph);

    const int M = BATCH * SEQ;          // 4096

    cudaFuncSetAttribute(gemm_mma<true>,  cudaFuncAttributeMaxDynamicSharedMemorySize, GSMEM_TOTAL);
    cudaFuncSetAttribute(gemm_mma<false>, cudaFuncAttributeMaxDynamicSharedMemorySize, GSMEM_TOTAL);
    cudaFuncSetAttribute(flash_mma,       cudaFuncAttributeMaxDynamicSharedMemorySize, FSMEM_TOTAL);

    // 0) splits / weight transposes (hi only)
    split_kernel<<<(M * DIM / 4 + 255) / 256, 256>>>(x, xhi, xlo, M * DIM / 4);
    {
        dim3 g1(3 * DIM / 32, DIM / 32);
        transpose_h<<<g1, 256>>>(Wqkv, wqh, DIM, 3 * DIM);
        dim3 g2(DIM / 32, DIM / 32);
        transpose_h<<<g2, 256>>>(Wproj, wph, DIM, DIM);
    }

    // 1) qkv = x @ Wqkv -> fp16 hi/lo (Q columns pre-scaled by SC2)
    {
        dim3 grid(3 * DIM / 128, M / 128);
        gemm_mma<true><<<grid, 256, GSMEM_TOTAL>>>(xhi, xlo, wqh,
                                                   nullptr, qh, ql, M, 3 * DIM, DIM);
    }

    // 2) flash attention -> fp16 hi/lo
    {
        dim3 grid(SEQ / 128, NHEAD, BATCH);
        flash_mma<<<grid, 256, FSMEM_TOTAL>>>(qh, ql, ahi, alo);
    }

    // 3) out = attn @ Wproj (fp32 out)
    {
        dim3 grid(DIM / 128, M / 128);
        gemm_mma<false><<<grid, 256, GSMEM_TOTAL>>>(ahi, alo, wph,
                                                    out, nullptr, nullptr, M, DIM, DIM);
    }
}